// round 1
// baseline (speedup 1.0000x reference)
#include <cuda_runtime.h>
#include <cstdint>

// Problem constants (fixed by the reference).
constexpr int N_TOK = 16384;
constexpr int K_CB  = 8192;
constexpr int D_DIM = 256;

// Tiling.
constexpr int BM = 128;   // rows (tokens) per CTA
constexpr int BN = 128;   // codes per code-tile
constexpr int BK = 16;    // depth chunk
constexpr int NSPLIT = 2; // K split across grid.y
constexpr int KPER = K_CB / NSPLIT;

// Scratch (allocation-free rule: __device__ globals).
__device__ float g_esq[K_CB];
__device__ float g_part_best[NSPLIT * N_TOK];
__device__ int   g_part_idx[NSPLIT * N_TOK];

// ---- packed fp32 helpers (sm_100+ f32x2 pipe, 2x FFMA throughput) ----
__device__ __forceinline__ unsigned long long ffma2(unsigned long long a,
                                                    unsigned long long b,
                                                    unsigned long long c) {
    unsigned long long d;
    asm("fma.rn.f32x2 %0, %1, %2, %3;" : "=l"(d) : "l"(a), "l"(b), "l"(c));
    return d;
}
__device__ __forceinline__ unsigned long long dup_f32(float x) {
    unsigned long long d;
    unsigned xi = __float_as_uint(x);
    asm("mov.b64 %0, {%1, %1};" : "=l"(d) : "r"(xi));
    return d;
}
__device__ __forceinline__ float lo_f32(unsigned long long v) {
    return __uint_as_float((unsigned)(v & 0xFFFFFFFFull));
}
__device__ __forceinline__ float hi_f32(unsigned long long v) {
    return __uint_as_float((unsigned)(v >> 32));
}

// ---- ||e_k||^2, one warp per codebook row ----
__global__ void esq_kernel(const float* __restrict__ E) {
    int gwarp = (blockIdx.x * blockDim.x + threadIdx.x) >> 5;
    int lane  = threadIdx.x & 31;
    if (gwarp >= K_CB) return;
    const float4* e = reinterpret_cast<const float4*>(E + (size_t)gwarp * D_DIM);
    float s = 0.f;
    float4 v = e[lane];
    s += v.x * v.x + v.y * v.y + v.z * v.z + v.w * v.w;
    v = e[lane + 32];
    s += v.x * v.x + v.y * v.y + v.z * v.z + v.w * v.w;
    #pragma unroll
    for (int o = 16; o > 0; o >>= 1) s += __shfl_xor_sync(0xFFFFFFFFu, s, o);
    if (lane == 0) g_esq[gwarp] = s;
}

// ---- main fused GEMM + running argmin ----
// grid: (N_TOK/BM, NSPLIT), block: 256 threads (16x16), micro-tile 8 rows x 8 cols,
// rows packed pairwise into f32x2 accumulators.
__global__ void __launch_bounds__(256, 2)
vq_argmin_kernel(const float* __restrict__ X, const float* __restrict__ E) {
    __shared__ float Xs[BK][BM];
    __shared__ float Es[BK][BN];
    __shared__ float sBest[BM][16];
    __shared__ int   sIdx[BM][16];

    const int tid = threadIdx.x;
    const int tx = tid & 15;   // column group
    const int ty = tid >> 4;   // row group
    const int rowBase = blockIdx.x * BM;
    const int split   = blockIdx.y;
    const int kBase0  = split * KPER;

    // Loader mapping: thread -> (row lr, col lc) covering a BMxBK tile with 2x float4.
    const int lr = tid >> 1;
    const int lc = (tid & 1) * 8;

    float best[8];
    int   bidx[8];
    #pragma unroll
    for (int i = 0; i < 8; i++) { best[i] = 3.402823466e38f; bidx[i] = 0; }

    for (int kt = 0; kt < KPER / BN; kt++) {
        const int colBase = kBase0 + kt * BN;

        unsigned long long acc[4][8];
        #pragma unroll
        for (int i = 0; i < 4; i++)
            #pragma unroll
            for (int j = 0; j < 8; j++) acc[i][j] = 0ull;

        for (int d0 = 0; d0 < D_DIM; d0 += BK) {
            // Stage X and E tiles (transposed to [k][m]) into shared.
            const float* xp = X + (size_t)(rowBase + lr) * D_DIM + d0 + lc;
            const float* ep = E + (size_t)(colBase + lr) * D_DIM + d0 + lc;
            float4 xv0 = *reinterpret_cast<const float4*>(xp);
            float4 xv1 = *reinterpret_cast<const float4*>(xp + 4);
            float4 ev0 = *reinterpret_cast<const float4*>(ep);
            float4 ev1 = *reinterpret_cast<const float4*>(ep + 4);
            Xs[lc + 0][lr] = xv0.x; Xs[lc + 1][lr] = xv0.y;
            Xs[lc + 2][lr] = xv0.z; Xs[lc + 3][lr] = xv0.w;
            Xs[lc + 4][lr] = xv1.x; Xs[lc + 5][lr] = xv1.y;
            Xs[lc + 6][lr] = xv1.z; Xs[lc + 7][lr] = xv1.w;
            Es[lc + 0][lr] = ev0.x; Es[lc + 1][lr] = ev0.y;
            Es[lc + 2][lr] = ev0.z; Es[lc + 3][lr] = ev0.w;
            Es[lc + 4][lr] = ev1.x; Es[lc + 5][lr] = ev1.y;
            Es[lc + 6][lr] = ev1.z; Es[lc + 7][lr] = ev1.w;
            __syncthreads();

            #pragma unroll
            for (int kk = 0; kk < BK; kk++) {
                // 8 rows -> 4 packed f32x2 operands.
                ulonglong2 a01 = *reinterpret_cast<const ulonglong2*>(&Xs[kk][ty * 8]);
                ulonglong2 a23 = *reinterpret_cast<const ulonglong2*>(&Xs[kk][ty * 8 + 4]);
                unsigned long long a[4] = { a01.x, a01.y, a23.x, a23.y };
                float4 bv0 = *reinterpret_cast<const float4*>(&Es[kk][tx * 8]);
                float4 bv1 = *reinterpret_cast<const float4*>(&Es[kk][tx * 8 + 4]);
                float bv[8] = { bv0.x, bv0.y, bv0.z, bv0.w, bv1.x, bv1.y, bv1.z, bv1.w };
                #pragma unroll
                for (int j = 0; j < 8; j++) {
                    unsigned long long bd = dup_f32(bv[j]);
                    #pragma unroll
                    for (int i = 0; i < 4; i++)
                        acc[i][j] = ffma2(a[i], bd, acc[i][j]);
                }
            }
            __syncthreads();
        }

        // Epilogue for this code tile: score = e_sq - 2*dot, running argmin.
        #pragma unroll
        for (int j = 0; j < 8; j++) {
            const int col = colBase + tx * 8 + j;
            const float es = g_esq[col];
            #pragma unroll
            for (int i = 0; i < 4; i++) {
                float s0 = fmaf(-2.0f, lo_f32(acc[i][j]), es);
                float s1 = fmaf(-2.0f, hi_f32(acc[i][j]), es);
                int r0 = 2 * i, r1 = 2 * i + 1;
                if (s0 < best[r0]) { best[r0] = s0; bidx[r0] = col; }
                if (s1 < best[r1]) { best[r1] = s1; bidx[r1] = col; }
            }
        }
    }

    // Cross-thread reduction: 16 column-group candidates per row.
    #pragma unroll
    for (int i = 0; i < 8; i++) {
        sBest[ty * 8 + i][tx] = best[i];
        sIdx[ty * 8 + i][tx]  = bidx[i];
    }
    __syncthreads();
    if (tid < BM) {
        float b = sBest[tid][0];
        int   bi = sIdx[tid][0];
        #pragma unroll
        for (int t = 1; t < 16; t++) {
            float v = sBest[tid][t];
            int  vi = sIdx[tid][t];
            if (v < b || (v == b && vi < bi)) { b = v; bi = vi; }
        }
        g_part_best[split * N_TOK + rowBase + tid] = b;
        g_part_idx [split * N_TOK + rowBase + tid] = bi;
    }
}

// ---- final: reduce splits, gather embed row, emit index ----
__global__ void vq_gather_kernel(const float* __restrict__ E,
                                 float* __restrict__ out, int write_idx) {
    const int row = blockIdx.x;
    float b0 = g_part_best[row];
    float b1 = g_part_best[N_TOK + row];
    int   i0 = g_part_idx[row];
    int   i1 = g_part_idx[N_TOK + row];
    int bi = (b1 < b0 || (b1 == b0 && i1 < i0)) ? i1 : i0;

    const float4* src = reinterpret_cast<const float4*>(E + (size_t)bi * D_DIM);
    float4* dst = reinterpret_cast<float4*>(out + (size_t)row * D_DIM);
    for (int i = threadIdx.x; i < D_DIM / 4; i += blockDim.x) dst[i] = src[i];
    if (write_idx && threadIdx.x == 0)
        out[(size_t)N_TOK * D_DIM + row] = (float)bi;
}

extern "C" void kernel_launch(void* const* d_in, const int* in_sizes, int n_in,
                              void* d_out, int out_size) {
    const float* X = (const float*)d_in[0];   // inputs_flatten [N, D]
    const float* E = (const float*)d_in[1];   // embed [K, D]
    float* out = (float*)d_out;

    esq_kernel<<<K_CB * 32 / 256, 256>>>(E);

    dim3 grid(N_TOK / BM, NSPLIT);
    vq_argmin_kernel<<<grid, 256>>>(X, E);

    // Output layout: quantize [N*D] then indices [N] (as float), if the buffer
    // has room for both; otherwise just quantize.
    int write_idx = (out_size >= N_TOK * D_DIM + N_TOK) ? 1 : 0;
    vq_gather_kernel<<<N_TOK, 64>>>(E, out, write_idx);
}

// round 6
// speedup vs baseline: 3.6264x; 3.6264x over previous
#include <cuda_runtime.h>
#include <cuda_bf16.h>
#include <cstdint>
#include <cfloat>

// Enable tcgen05 only on arch-specific (sm_10xa) compilation passes; the plain
// compute_103 pass compiles a stub (runtime falls back to exact scan).
#if defined(__CUDA_ARCH__) && (defined(__CUDA_ARCH_FEAT_SM103_ALL) || defined(__CUDA_ARCH_FEAT_SM100_ALL) || defined(__CUDA_ARCH_FEAT_SM101_ALL))
#define HAS_TCGEN05 1
#else
#define HAS_TCGEN05 0
#endif

// ---------------- problem constants ----------------
constexpr int N_TOK = 16384;
constexpr int K_CB  = 8192;
constexpr int D_DIM = 256;

constexpr int BM = 128;                 // tokens per CTA (M tile)
constexpr int BN = 128;                 // codes per chunk (N tile)
constexpr int NCHUNK = K_CB / BN;       // 64
constexpr int CAP = 128;                // candidate slots per token
constexpr float MARGIN = 2.0f;          // >> 2 * max bf16 distance error

// ---------------- device scratch (no runtime alloc allowed) ----------------
__device__ __align__(16) __nv_bfloat16 g_Xb[N_TOK * D_DIM];
__device__ __align__(16) __nv_bfloat16 g_Eb[K_CB * D_DIM];
__device__ float g_esq[K_CB];
__device__ int   g_cand_idx[N_TOK * CAP];
__device__ int   g_cand_cnt[N_TOK];

// ---------------- PTX helpers ----------------
__device__ __forceinline__ uint32_t smem_u32(const void* p) {
    uint32_t a;
    asm("{ .reg .u64 t; cvta.to.shared.u64 t, %1; cvt.u32.u64 %0, t; }" : "=r"(a) : "l"(p));
    return a;
}

#if HAS_TCGEN05
__device__ __forceinline__ uint32_t elect_one() {
    uint32_t p;
    asm volatile("{ .reg .pred p; elect.sync _|p, 0xFFFFFFFF; selp.b32 %0, 1, 0, p; }" : "=r"(p));
    return p;
}
#define MBAR_INIT(a, n) asm volatile("mbarrier.init.shared.b64 [%0], %1;" :: "r"(a), "r"(n) : "memory")
#define MBAR_ARRIVE(a)  asm volatile("mbarrier.arrive.shared.b64 _, [%0];" :: "r"(a) : "memory")
#define MBAR_WAIT(a, ph) do {                                                         \
    uint32_t _m = (a); uint32_t _p = (ph); uint32_t _d;                               \
    asm volatile("{ .reg .pred p; mbarrier.try_wait.parity.acquire.cta.shared::cta.b64 p, [%1], %2; selp.b32 %0, 1, 0, p; }" \
        : "=r"(_d) : "r"(_m), "r"(_p) : "memory");                                    \
    if (!_d) {                                                                        \
        asm volatile("{ .reg .pred P1; WL_%=: mbarrier.try_wait.parity.acquire.cta.shared::cta.b64 P1, [%0], %1, 0x989680; @P1 bra.uni WD_%=; bra.uni WL_%=; WD_%=: }" \
            :: "r"(_m), "r"(_p) : "memory");                                          \
    }                                                                                 \
} while (0)

#define TC_ALLOC(sa, n)   asm volatile("tcgen05.alloc.cta_group::1.sync.aligned.shared::cta.b32 [%0], %1;" :: "r"(sa), "r"(n) : "memory")
#define TC_DEALLOC(t, n)  asm volatile("tcgen05.dealloc.cta_group::1.sync.aligned.b32 %0, %1;" :: "r"(t), "r"(n))
#define TC_RELINQ()       asm volatile("tcgen05.relinquish_alloc_permit.cta_group::1.sync.aligned;")
#define TC_COMMIT(mb)     asm volatile("tcgen05.commit.cta_group::1.mbarrier::arrive::one.shared::cluster.b64 [%0];" :: "r"(mb) : "memory")
#define TC_FENCE_BEFORE() asm volatile("tcgen05.fence::before_thread_sync;" ::: "memory")
#define TC_FENCE_AFTER()  asm volatile("tcgen05.fence::after_thread_sync;" ::: "memory")
#define TC_WAIT_LD()      asm volatile("tcgen05.wait::ld.sync.aligned;" ::: "memory")
#define FENCE_ASYNC()     asm volatile("fence.proxy.async.shared::cta;" ::: "memory")

#define TC_LD_X32(r, ta) \
    asm volatile( \
        "tcgen05.ld.sync.aligned.32x32b.x32.b32 " \
        "{%0, %1, %2, %3, %4, %5, %6, %7, " \
        " %8, %9, %10, %11, %12, %13, %14, %15, " \
        " %16, %17, %18, %19, %20, %21, %22, %23, " \
        " %24, %25, %26, %27, %28, %29, %30, %31}, [%32];" \
        : "=r"((r)[0]),  "=r"((r)[1]),  "=r"((r)[2]),  "=r"((r)[3]), \
          "=r"((r)[4]),  "=r"((r)[5]),  "=r"((r)[6]),  "=r"((r)[7]), \
          "=r"((r)[8]),  "=r"((r)[9]),  "=r"((r)[10]), "=r"((r)[11]), \
          "=r"((r)[12]), "=r"((r)[13]), "=r"((r)[14]), "=r"((r)[15]), \
          "=r"((r)[16]), "=r"((r)[17]), "=r"((r)[18]), "=r"((r)[19]), \
          "=r"((r)[20]), "=r"((r)[21]), "=r"((r)[22]), "=r"((r)[23]), \
          "=r"((r)[24]), "=r"((r)[25]), "=r"((r)[26]), "=r"((r)[27]), \
          "=r"((r)[28]), "=r"((r)[29]), "=r"((r)[30]), "=r"((r)[31]) \
        : "r"(ta))

// SS-mode bf16 MMA, cta_group::1
__device__ __forceinline__ void mma_f16_ss(uint32_t d, uint64_t a, uint64_t b,
                                           uint32_t idesc, bool acc) {
    uint32_t en = acc ? 1u : 0u;
    asm volatile(
        "{\n\t.reg .pred p;\n\tsetp.ne.u32 p, %4, 0;\n\t"
        "tcgen05.mma.cta_group::1.kind::f16 [%0], %1, %2, %3, {%5,%5,%5,%5}, p;\n\t}"
        :: "r"(d), "l"(a), "l"(b), "r"(idesc), "r"(en), "r"(0u) : "memory");
}
#endif // HAS_TCGEN05

// SW128 K-major SMEM descriptor base (layout=SW128, version=1, SBO=64, LBO=1)
constexpr uint64_t DESC_BASE =
    (uint64_t(2) << 61) | (uint64_t(1) << 46) | (uint64_t(64) << 32) | (uint64_t(1) << 16);
__device__ __forceinline__ uint64_t make_desc(uint32_t smem_addr) {
    return DESC_BASE | ((uint64_t)(smem_addr >> 4) & 0x3FFF);
}

// idesc: f32 accum, bf16 A/B, K-major both, M=128, N=128
constexpr uint32_t MMA_IDESC =
    (1u << 4) | (1u << 7) | (1u << 10) | ((BN / 8) << 17) | ((BM / 16) << 24); // 0x8200490

// Blocked-atom SW128 layout for a 128-row x 512-byte (256 bf16) tile.
// Atom = 8 rows x 128 B; 16 atom-rows, 4 atom-cols; atom_off = atom_col*16 + atom_row.
__device__ __forceinline__ uint32_t tile_off(int row, int bytecol) {
    uint32_t off = (uint32_t)((((bytecol >> 7) << 4) + (row >> 3)) << 10)
                 + (uint32_t)((row & 7) << 7) + (uint32_t)(bytecol & 127);
    return off ^ ((off >> 3) & 0x70);
}
// descriptor K-step offset (16-byte units) for kstep in [0,16): 16 bf16 per step
__device__ __forceinline__ uint32_t kstep_units(int k) {
    return (uint32_t)((k >> 2) * 1024 + (k & 3) * 2);
}

// ---------------- SMEM layout (offsets from the 1024-aligned base) ----------------
constexpr int SM_TMEMP = 0;
constexpr int SM_FULL0 = 8,  SM_FULL1 = 16;
constexpr int SM_MMA0  = 24, SM_MMA1  = 32;
constexpr int SM_EPI0  = 40, SM_EPI1  = 48;
constexpr int SM_X     = 1024;
constexpr int TILE_BYTES = BM * D_DIM * 2;        // 65536
constexpr int SM_E0    = SM_X + TILE_BYTES;
constexpr int SM_E1    = SM_E0 + TILE_BYTES;
constexpr int SMEM_TOTAL = SM_E1 + TILE_BYTES + 1024;   // +1024 alignment slack

// ---------------- prep kernels ----------------
__global__ void prep_x(const float* __restrict__ X) {
    int i = blockIdx.x * blockDim.x + threadIdx.x;          // one uint4 (8 bf16) each
    const float4* s = reinterpret_cast<const float4*>(X) + (size_t)i * 2;
    float4 a = s[0], b = s[1];
    __nv_bfloat162 h0 = __floats2bfloat162_rn(a.x, a.y);
    __nv_bfloat162 h1 = __floats2bfloat162_rn(a.z, a.w);
    __nv_bfloat162 h2 = __floats2bfloat162_rn(b.x, b.y);
    __nv_bfloat162 h3 = __floats2bfloat162_rn(b.z, b.w);
    uint4 o;
    o.x = *reinterpret_cast<uint32_t*>(&h0);
    o.y = *reinterpret_cast<uint32_t*>(&h1);
    o.z = *reinterpret_cast<uint32_t*>(&h2);
    o.w = *reinterpret_cast<uint32_t*>(&h3);
    reinterpret_cast<uint4*>(g_Xb)[i] = o;
}

__global__ void prep_e(const float* __restrict__ E) {
    int gw = (blockIdx.x * blockDim.x + threadIdx.x) >> 5;
    int lane = threadIdx.x & 31;
    if (gw >= K_CB) return;
    const float4* e = reinterpret_cast<const float4*>(E + (size_t)gw * D_DIM);
    float4 v0 = e[lane], v1 = e[lane + 32];
    float s = v0.x * v0.x + v0.y * v0.y + v0.z * v0.z + v0.w * v0.w
            + v1.x * v1.x + v1.y * v1.y + v1.z * v1.z + v1.w * v1.w;
    __nv_bfloat162 h0 = __floats2bfloat162_rn(v0.x, v0.y);
    __nv_bfloat162 h1 = __floats2bfloat162_rn(v0.z, v0.w);
    __nv_bfloat162 h2 = __floats2bfloat162_rn(v1.x, v1.y);
    __nv_bfloat162 h3 = __floats2bfloat162_rn(v1.z, v1.w);
    uint2 o0 = { *reinterpret_cast<uint32_t*>(&h0), *reinterpret_cast<uint32_t*>(&h1) };
    uint2 o1 = { *reinterpret_cast<uint32_t*>(&h2), *reinterpret_cast<uint32_t*>(&h3) };
    *reinterpret_cast<uint2*>(g_Eb + (size_t)gw * D_DIM + lane * 4) = o0;
    *reinterpret_cast<uint2*>(g_Eb + (size_t)gw * D_DIM + 128 + lane * 4) = o1;
    #pragma unroll
    for (int o = 16; o > 0; o >>= 1) s += __shfl_xor_sync(0xFFFFFFFFu, s, o);
    if (lane == 0) g_esq[gw] = s;
}

// ---------------- stage 1: tcgen05 bf16 GEMM + margin-argmin ----------------
__global__ void __launch_bounds__(256, 1)
vq_stage1() {
    const int tid = threadIdx.x;
    const int rowBase = blockIdx.x * BM;
#if HAS_TCGEN05
    extern __shared__ char smem_raw[];
    const uint32_t sb0 = smem_u32(smem_raw);
    const uint32_t sb = (sb0 + 1023u) & ~1023u;        // 1024-aligned base for SW128
    char* smem = smem_raw + (sb - sb0);
    const int wid = tid >> 5;

    if (wid == 4) {
        TC_ALLOC(sb + SM_TMEMP, 256);
        TC_RELINQ();
    }
    if (tid == 0) {
        MBAR_INIT(sb + SM_FULL0, 96); MBAR_INIT(sb + SM_FULL1, 96);
        MBAR_INIT(sb + SM_MMA0, 1);   MBAR_INIT(sb + SM_MMA1, 1);
        MBAR_INIT(sb + SM_EPI0, 128); MBAR_INIT(sb + SM_EPI1, 128);
    }
    __syncthreads();
    uint32_t tmem;
    asm volatile("ld.shared.b32 %0, [%1];" : "=r"(tmem) : "r"(sb + SM_TMEMP));

    // Stage X tile (128 x 256 bf16) once; all 256 threads.
    for (int i = tid; i < 4096; i += 256) {
        int row = i >> 5, c16 = i & 31;
        uint4 v = *reinterpret_cast<const uint4*>(g_Xb + (size_t)(rowBase + row) * D_DIM + c16 * 8);
        *reinterpret_cast<uint4*>(smem + SM_X + tile_off(row, c16 * 16)) = v;
    }
    FENCE_ASYNC();
    __syncthreads();

    if (wid < 4) {
        // ---------------- epilogue warps: one token row per thread ----------------
        const int token = rowBase + tid;
        float best = FLT_MAX;
        int cnt = 0;
        for (int c = 0; c < NCHUNK; c++) {
            const int s = c & 1;
            MBAR_WAIT(sb + (s ? SM_MMA1 : SM_MMA0), (c >> 1) & 1);
            TC_FENCE_AFTER();
            #pragma unroll
            for (int b = 0; b < 4; b++) {
                uint32_t r[32];
                TC_LD_X32(r, tmem + (uint32_t)(s * BN) + b * 32);
                TC_WAIT_LD();
                const int colBase = c * BN + b * 32;
                #pragma unroll
                for (int j = 0; j < 32; j++) {
                    float sc = fmaf(-2.0f, __uint_as_float(r[j]), __ldg(&g_esq[colBase + j]));
                    if (sc < best + MARGIN) {
                        if (cnt < CAP) g_cand_idx[(size_t)token * CAP + cnt] = colBase + j;
                        cnt++;
                        if (sc < best) best = sc;
                    }
                }
            }
            TC_FENCE_BEFORE();
            MBAR_ARRIVE(sb + (s ? SM_EPI1 : SM_EPI0));
        }
        g_cand_cnt[token] = cnt;
    } else if (wid == 4) {
        // ---------------- MMA warp ----------------
        const uint64_t a_base = make_desc(sb + SM_X);
        for (int c = 0; c < NCHUNK; c++) {
            const int s = c & 1;
            MBAR_WAIT(sb + (s ? SM_FULL1 : SM_FULL0), (c >> 1) & 1);
            if (c >= 2) MBAR_WAIT(sb + (s ? SM_EPI1 : SM_EPI0), ((c - 2) >> 1) & 1);
            TC_FENCE_AFTER();
            if (elect_one()) {
                const uint64_t b_base = make_desc(sb + (s ? SM_E1 : SM_E0));
                #pragma unroll
                for (int k = 0; k < 16; k++) {
                    uint32_t u = kstep_units(k);
                    mma_f16_ss(tmem + (uint32_t)(s * BN), a_base + u, b_base + u,
                               MMA_IDESC, k > 0);
                }
                TC_COMMIT(sb + (s ? SM_MMA1 : SM_MMA0));
            }
        }
    } else {
        // ---------------- loader warps (5..7, 96 threads) ----------------
        const int lt = tid - 160;
        for (int c = 0; c < NCHUNK; c++) {
            const int s = c & 1;
            if (c >= 2) MBAR_WAIT(sb + (s ? SM_MMA1 : SM_MMA0), ((c - 2) >> 1) & 1);
            const int eoff = s ? SM_E1 : SM_E0;
            const size_t gbase = (size_t)(c * BN) * D_DIM;
            for (int i = lt; i < 4096; i += 96) {
                int row = i >> 5, c16 = i & 31;
                uint4 v = *reinterpret_cast<const uint4*>(g_Eb + gbase + (size_t)row * D_DIM + c16 * 8);
                *reinterpret_cast<uint4*>(smem + eoff + tile_off(row, c16 * 16)) = v;
            }
            FENCE_ASYNC();
            MBAR_ARRIVE(sb + (s ? SM_FULL1 : SM_FULL0));
        }
    }

    __syncthreads();
    if (wid == 4) TC_DEALLOC(tmem, 256);
#else
    // Stub pass (compute_103 without arch features): force stage-2 exact full
    // scan for every token so results stay correct if this cubin is loaded.
    if (tid < BM) g_cand_cnt[rowBase + tid] = CAP + 1;
#endif
}

// ---------------- stage 2: exact fp32 rescore of candidates + gather ----------------
__global__ void vq_stage2(const float* __restrict__ X, const float* __restrict__ E,
                          float* __restrict__ out, int write_idx) {
    const int warp = (blockIdx.x * blockDim.x + threadIdx.x) >> 5;
    const int lane = threadIdx.x & 31;
    if (warp >= N_TOK) return;

    const float4* xr = reinterpret_cast<const float4*>(X + (size_t)warp * D_DIM) + lane * 2;
    const float4 x0 = xr[0], x1 = xr[1];

    int cnt = g_cand_cnt[warp];
    float best = FLT_MAX;
    int bi = 0;

    auto score = [&](int k) -> float {
        const float4* er = reinterpret_cast<const float4*>(E + (size_t)k * D_DIM) + lane * 2;
        float4 e0 = er[0], e1 = er[1];
        float d = x0.x * e0.x;
        d = fmaf(x0.y, e0.y, d); d = fmaf(x0.z, e0.z, d); d = fmaf(x0.w, e0.w, d);
        d = fmaf(x1.x, e1.x, d); d = fmaf(x1.y, e1.y, d);
        d = fmaf(x1.z, e1.z, d); d = fmaf(x1.w, e1.w, d);
        #pragma unroll
        for (int o = 16; o > 0; o >>= 1) d += __shfl_xor_sync(0xFFFFFFFFu, d, o);
        return fmaf(-2.0f, d, __ldg(&g_esq[k]));
    };

    if (cnt <= CAP) {
        for (int t = 0; t < cnt; t++) {
            int k = g_cand_idx[(size_t)warp * CAP + t];
            float sc = score(k);
            if (sc < best) { best = sc; bi = k; }   // ascending k -> first occurrence on ties
        }
    } else {
        // overflow / stub fallback: exact scan of all codes
        for (int k = 0; k < K_CB; k++) {
            float sc = score(k);
            if (sc < best) { best = sc; bi = k; }
        }
    }

    const float4* er = reinterpret_cast<const float4*>(E + (size_t)bi * D_DIM) + lane * 2;
    float4* outr = reinterpret_cast<float4*>(out + (size_t)warp * D_DIM) + lane * 2;
    outr[0] = er[0];
    outr[1] = er[1];
    if (write_idx && lane == 0)
        out[(size_t)N_TOK * D_DIM + warp] = (float)bi;
}

// ---------------- launcher ----------------
extern "C" void kernel_launch(void* const* d_in, const int* in_sizes, int n_in,
                              void* d_out, int out_size) {
    const float* X = (const float*)d_in[0];   // inputs_flatten [N, D]
    const float* E = (const float*)d_in[1];   // embed [K, D]
    float* out = (float*)d_out;

    cudaFuncSetAttribute(vq_stage1, cudaFuncAttributeMaxDynamicSharedMemorySize, SMEM_TOTAL);

    prep_x<<<(N_TOK * D_DIM / 8) / 256, 256>>>(X);
    prep_e<<<(K_CB * 32) / 256, 256>>>(E);
    vq_stage1<<<N_TOK / BM, 256, SMEM_TOTAL>>>();

    int write_idx = (out_size >= N_TOK * D_DIM + N_TOK) ? 1 : 0;
    vq_stage2<<<(N_TOK / 8), 256>>>(X, E, out, write_idx);
}

// round 7
// speedup vs baseline: 5.6666x; 1.5626x over previous
#include <cuda_runtime.h>
#include <cuda_bf16.h>
#include <cstdint>
#include <cfloat>

// Enable tcgen05 only on arch-specific (sm_10xa) compilation passes; the plain
// compute_103 pass compiles a stub (runtime falls back to exact scan).
#if defined(__CUDA_ARCH__) && (defined(__CUDA_ARCH_FEAT_SM103_ALL) || defined(__CUDA_ARCH_FEAT_SM100_ALL) || defined(__CUDA_ARCH_FEAT_SM101_ALL))
#define HAS_TCGEN05 1
#else
#define HAS_TCGEN05 0
#endif

// ---------------- problem constants ----------------
constexpr int N_TOK = 16384;
constexpr int K_CB  = 8192;
constexpr int D_DIM = 256;

constexpr int BM = 128;                 // tokens per CTA (M tile)
constexpr int BN = 128;                 // codes per chunk (N tile)
constexpr int NCHUNK = K_CB / BN;       // 64
constexpr int CAP_H = 64;               // candidate slots per (token, half)
constexpr float MARGIN = 2.0f;          // >> 2 * max bf16 distance error

// ---------------- device scratch ----------------
__device__ __align__(16) __nv_bfloat16 g_Xb[N_TOK * D_DIM];
__device__ __align__(16) __nv_bfloat16 g_Eb[K_CB * D_DIM];
__device__ float g_esq[K_CB];
__device__ int   g_cand_idx[N_TOK * 2 * CAP_H];
__device__ int   g_cand_cnt[N_TOK * 2];

// ---------------- PTX helpers ----------------
__device__ __forceinline__ uint32_t smem_u32(const void* p) {
    uint32_t a;
    asm("{ .reg .u64 t; cvta.to.shared.u64 t, %1; cvt.u32.u64 %0, t; }" : "=r"(a) : "l"(p));
    return a;
}

#if HAS_TCGEN05
__device__ __forceinline__ uint32_t elect_one() {
    uint32_t p;
    asm volatile("{ .reg .pred p; elect.sync _|p, 0xFFFFFFFF; selp.b32 %0, 1, 0, p; }" : "=r"(p));
    return p;
}
#define MBAR_INIT(a, n) asm volatile("mbarrier.init.shared.b64 [%0], %1;" :: "r"(a), "r"(n) : "memory")
#define MBAR_ARRIVE(a)  asm volatile("mbarrier.arrive.release.cta.shared::cta.b64 _, [%0];" :: "r"(a) : "memory")
#define MBAR_WAIT(a, ph) do {                                                         \
    uint32_t _m = (a); uint32_t _p = (ph); uint32_t _d;                               \
    asm volatile("{ .reg .pred p; mbarrier.try_wait.parity.acquire.cta.shared::cta.b64 p, [%1], %2; selp.b32 %0, 1, 0, p; }" \
        : "=r"(_d) : "r"(_m), "r"(_p) : "memory");                                    \
    if (!_d) {                                                                        \
        asm volatile("{ .reg .pred P1; WL_%=: mbarrier.try_wait.parity.acquire.cta.shared::cta.b64 P1, [%0], %1, 0x989680; @P1 bra.uni WD_%=; bra.uni WL_%=; WD_%=: }" \
            :: "r"(_m), "r"(_p) : "memory");                                          \
    }                                                                                 \
} while (0)

#define TC_ALLOC(sa, n)   asm volatile("tcgen05.alloc.cta_group::1.sync.aligned.shared::cta.b32 [%0], %1;" :: "r"(sa), "r"(n) : "memory")
#define TC_DEALLOC(t, n)  asm volatile("tcgen05.dealloc.cta_group::1.sync.aligned.b32 %0, %1;" :: "r"(t), "r"(n))
#define TC_RELINQ()       asm volatile("tcgen05.relinquish_alloc_permit.cta_group::1.sync.aligned;")
#define TC_COMMIT(mb)     asm volatile("tcgen05.commit.cta_group::1.mbarrier::arrive::one.shared::cluster.b64 [%0];" :: "r"(mb) : "memory")
#define TC_FENCE_BEFORE() asm volatile("tcgen05.fence::before_thread_sync;" ::: "memory")
#define TC_FENCE_AFTER()  asm volatile("tcgen05.fence::after_thread_sync;" ::: "memory")
#define TC_WAIT_LD()      asm volatile("tcgen05.wait::ld.sync.aligned;" ::: "memory")
#define FENCE_ASYNC()     asm volatile("fence.proxy.async.shared::cta;" ::: "memory")

#define TC_LD_X32(r, ta) \
    asm volatile( \
        "tcgen05.ld.sync.aligned.32x32b.x32.b32 " \
        "{%0, %1, %2, %3, %4, %5, %6, %7, " \
        " %8, %9, %10, %11, %12, %13, %14, %15, " \
        " %16, %17, %18, %19, %20, %21, %22, %23, " \
        " %24, %25, %26, %27, %28, %29, %30, %31}, [%32];" \
        : "=r"((r)[0]),  "=r"((r)[1]),  "=r"((r)[2]),  "=r"((r)[3]), \
          "=r"((r)[4]),  "=r"((r)[5]),  "=r"((r)[6]),  "=r"((r)[7]), \
          "=r"((r)[8]),  "=r"((r)[9]),  "=r"((r)[10]), "=r"((r)[11]), \
          "=r"((r)[12]), "=r"((r)[13]), "=r"((r)[14]), "=r"((r)[15]), \
          "=r"((r)[16]), "=r"((r)[17]), "=r"((r)[18]), "=r"((r)[19]), \
          "=r"((r)[20]), "=r"((r)[21]), "=r"((r)[22]), "=r"((r)[23]), \
          "=r"((r)[24]), "=r"((r)[25]), "=r"((r)[26]), "=r"((r)[27]), \
          "=r"((r)[28]), "=r"((r)[29]), "=r"((r)[30]), "=r"((r)[31]) \
        : "r"(ta))

// SS-mode bf16 MMA, cta_group::1
__device__ __forceinline__ void mma_f16_ss(uint32_t d, uint64_t a, uint64_t b,
                                           uint32_t idesc, bool acc) {
    uint32_t en = acc ? 1u : 0u;
    asm volatile(
        "{\n\t.reg .pred p;\n\tsetp.ne.u32 p, %4, 0;\n\t"
        "tcgen05.mma.cta_group::1.kind::f16 [%0], %1, %2, %3, {%5,%5,%5,%5}, p;\n\t}"
        :: "r"(d), "l"(a), "l"(b), "r"(idesc), "r"(en), "r"(0u) : "memory");
}
#endif // HAS_TCGEN05

// SW128 K-major SMEM descriptor base (layout=SW128, version=1, SBO=64, LBO=1)
constexpr uint64_t DESC_BASE =
    (uint64_t(2) << 61) | (uint64_t(1) << 46) | (uint64_t(64) << 32) | (uint64_t(1) << 16);
__device__ __forceinline__ uint64_t make_desc(uint32_t smem_addr) {
    return DESC_BASE | ((uint64_t)(smem_addr >> 4) & 0x3FFF);
}

// idesc: f32 accum, bf16 A/B, K-major both, M=128, N=128
constexpr uint32_t MMA_IDESC =
    (1u << 4) | (1u << 7) | (1u << 10) | ((BN / 8) << 17) | ((BM / 16) << 24);

// Blocked-atom SW128 layout for a 128-row x 512-byte (256 bf16) tile.
__device__ __forceinline__ uint32_t tile_off(int row, int bytecol) {
    uint32_t off = (uint32_t)((((bytecol >> 7) << 4) + (row >> 3)) << 10)
                 + (uint32_t)((row & 7) << 7) + (uint32_t)(bytecol & 127);
    return off ^ ((off >> 3) & 0x70);
}
__device__ __forceinline__ uint32_t kstep_units(int k) {
    return (uint32_t)((k >> 2) * 1024 + (k & 3) * 2);
}

// ---------------- SMEM layout (offsets from the 1024-aligned base) ----------------
constexpr int SM_TMEMP = 0;
constexpr int SM_FULL0 = 8,  SM_FULL1 = 16;
constexpr int SM_MMA0  = 24, SM_MMA1  = 32;
constexpr int SM_EPI0  = 40, SM_EPI1  = 48;
constexpr int SM_ESQ0  = 64;                        // 512 B
constexpr int SM_ESQ1  = SM_ESQ0 + 512;             // 512 B
constexpr int SM_X     = 2048;
constexpr int TILE_BYTES = BM * D_DIM * 2;          // 65536
constexpr int SM_E0    = SM_X + TILE_BYTES;
constexpr int SM_E1    = SM_E0 + TILE_BYTES;
constexpr int SMEM_TOTAL = SM_E1 + TILE_BYTES + 1024;   // alignment slack

constexpr int NTHREADS = 384;   // 8 epi warps + 1 MMA + 3 loaders

// ---------------- prep kernels ----------------
__global__ void prep_x(const float* __restrict__ X) {
    int i = blockIdx.x * blockDim.x + threadIdx.x;          // one uint4 (8 bf16) each
    const float4* s = reinterpret_cast<const float4*>(X) + (size_t)i * 2;
    float4 a = s[0], b = s[1];
    __nv_bfloat162 h0 = __floats2bfloat162_rn(a.x, a.y);
    __nv_bfloat162 h1 = __floats2bfloat162_rn(a.z, a.w);
    __nv_bfloat162 h2 = __floats2bfloat162_rn(b.x, b.y);
    __nv_bfloat162 h3 = __floats2bfloat162_rn(b.z, b.w);
    uint4 o;
    o.x = *reinterpret_cast<uint32_t*>(&h0);
    o.y = *reinterpret_cast<uint32_t*>(&h1);
    o.z = *reinterpret_cast<uint32_t*>(&h2);
    o.w = *reinterpret_cast<uint32_t*>(&h3);
    reinterpret_cast<uint4*>(g_Xb)[i] = o;
}

__global__ void prep_e(const float* __restrict__ E) {
    int gw = (blockIdx.x * blockDim.x + threadIdx.x) >> 5;
    int lane = threadIdx.x & 31;
    if (gw >= K_CB) return;
    const float4* e = reinterpret_cast<const float4*>(E + (size_t)gw * D_DIM);
    float4 v0 = e[lane], v1 = e[lane + 32];
    float s = v0.x * v0.x + v0.y * v0.y + v0.z * v0.z + v0.w * v0.w
            + v1.x * v1.x + v1.y * v1.y + v1.z * v1.z + v1.w * v1.w;
    __nv_bfloat162 h0 = __floats2bfloat162_rn(v0.x, v0.y);
    __nv_bfloat162 h1 = __floats2bfloat162_rn(v0.z, v0.w);
    __nv_bfloat162 h2 = __floats2bfloat162_rn(v1.x, v1.y);
    __nv_bfloat162 h3 = __floats2bfloat162_rn(v1.z, v1.w);
    uint2 o0 = { *reinterpret_cast<uint32_t*>(&h0), *reinterpret_cast<uint32_t*>(&h1) };
    uint2 o1 = { *reinterpret_cast<uint32_t*>(&h2), *reinterpret_cast<uint32_t*>(&h3) };
    *reinterpret_cast<uint2*>(g_Eb + (size_t)gw * D_DIM + lane * 4) = o0;
    *reinterpret_cast<uint2*>(g_Eb + (size_t)gw * D_DIM + 128 + lane * 4) = o1;
    #pragma unroll
    for (int o = 16; o > 0; o >>= 1) s += __shfl_xor_sync(0xFFFFFFFFu, s, o);
    if (lane == 0) g_esq[gw] = s;
}

// ---------------- stage 1 ----------------
__global__ void __launch_bounds__(NTHREADS, 1)
vq_stage1() {
    const int tid = threadIdx.x;
    const int rowBase = blockIdx.x * BM;
#if HAS_TCGEN05
    extern __shared__ char smem_raw[];
    const uint32_t sb0 = smem_u32(smem_raw);
    const uint32_t sb = (sb0 + 1023u) & ~1023u;        // 1024-aligned base
    char* smem = smem_raw + (sb - sb0);
    const int wid = tid >> 5;
    const int lane = tid & 31;

    if (wid == 8) {
        TC_ALLOC(sb + SM_TMEMP, 256);
        TC_RELINQ();
    }
    if (tid == 0) {
        MBAR_INIT(sb + SM_FULL0, 96);  MBAR_INIT(sb + SM_FULL1, 96);
        MBAR_INIT(sb + SM_MMA0, 1);    MBAR_INIT(sb + SM_MMA1, 1);
        MBAR_INIT(sb + SM_EPI0, 256);  MBAR_INIT(sb + SM_EPI1, 256);
    }
    __syncthreads();
    uint32_t tmem;
    asm volatile("ld.shared.b32 %0, [%1];" : "=r"(tmem) : "r"(sb + SM_TMEMP));

    // Stage X tile (128 x 256 bf16) once; all threads.
    for (int i = tid; i < 4096; i += NTHREADS) {
        int row = i >> 5, c16 = i & 31;
        uint4 v = *reinterpret_cast<const uint4*>(g_Xb + (size_t)(rowBase + row) * D_DIM + c16 * 8);
        *reinterpret_cast<uint4*>(smem + SM_X + tile_off(row, c16 * 16)) = v;
    }
    FENCE_ASYNC();
    __syncthreads();

    if (wid < 8) {
        // ---- epilogue warps: warp -> subpartition (wid&3) rows, (wid>>2) col half ----
        const int half  = wid >> 2;               // 0: cols 0-63, 1: cols 64-127
        const int token = rowBase + (wid & 3) * 32 + lane;
        float best = FLT_MAX;
        int cnt = 0;
        int* mylist = g_cand_idx + ((size_t)token * 2 + half) * CAP_H;

        for (int c = 0; c < NCHUNK; c++) {
            const int s = c & 1;
            const int ph = (c >> 1) & 1;
            MBAR_WAIT(sb + (s ? SM_MMA1 : SM_MMA0), ph);
            TC_FENCE_AFTER();

            uint32_t r[64];
            const uint32_t tbase = tmem + (uint32_t)(s * 128 + half * 64);
            TC_LD_X32(r, tbase);
            TC_LD_X32(r + 32, tbase + 32);

            // esq for my 64 columns from SMEM (broadcast reads).
            const float4* esm = reinterpret_cast<const float4*>(
                smem + (s ? SM_ESQ1 : SM_ESQ0) + half * 256);
            TC_WAIT_LD();

            // Fold esq into scores in-place (forces LDS + LDTM completion).
            float* sc = reinterpret_cast<float*>(r);
            #pragma unroll
            for (int g = 0; g < 16; g++) {
                float4 e = esm[g];
                sc[g*4+0] = fmaf(-2.0f, __uint_as_float(r[g*4+0]), e.x);
                sc[g*4+1] = fmaf(-2.0f, __uint_as_float(r[g*4+1]), e.y);
                sc[g*4+2] = fmaf(-2.0f, __uint_as_float(r[g*4+2]), e.z);
                sc[g*4+3] = fmaf(-2.0f, __uint_as_float(r[g*4+3]), e.w);
            }
            TC_FENCE_BEFORE();
            MBAR_ARRIVE(sb + (s ? SM_EPI1 : SM_EPI0));   // release TMEM + esq early

            // Tree-min over the 64 scores (parallel, no serial chain).
            float m = sc[0];
            #pragma unroll
            for (int j = 1; j < 64; j++) m = fminf(m, sc[j]);

            if (m < best + MARGIN) {          // rare: collect candidates
                const int colBase = c * BN + half * 64;
                #pragma unroll 4
                for (int j = 0; j < 64; j++) {
                    float v = sc[j];
                    if (v < best + MARGIN) {
                        if (cnt < CAP_H) mylist[cnt] = colBase + j;
                        cnt++;
                        if (v < best) best = v;
                    }
                }
            }
        }
        g_cand_cnt[(size_t)token * 2 + half] = cnt;
    } else if (wid == 8) {
        // ---- MMA warp ----
        const uint64_t a_base = make_desc(sb + SM_X);
        for (int c = 0; c < NCHUNK; c++) {
            const int s = c & 1;
            MBAR_WAIT(sb + (s ? SM_FULL1 : SM_FULL0), (c >> 1) & 1);
            if (c >= 2) MBAR_WAIT(sb + (s ? SM_EPI1 : SM_EPI0), ((c - 2) >> 1) & 1);
            TC_FENCE_AFTER();
            if (elect_one()) {
                const uint64_t b_base = make_desc(sb + (s ? SM_E1 : SM_E0));
                #pragma unroll
                for (int k = 0; k < 16; k++) {
                    uint32_t u = kstep_units(k);
                    mma_f16_ss(tmem + (uint32_t)(s * 128), a_base + u, b_base + u,
                               MMA_IDESC, k > 0);
                }
                TC_COMMIT(sb + (s ? SM_MMA1 : SM_MMA0));
            }
        }
    } else {
        // ---- loader warps (9..11, 96 threads) ----
        const int lt = tid - 288;
        for (int c = 0; c < NCHUNK; c++) {
            const int s = c & 1;
            if (c >= 2) MBAR_WAIT(sb + (s ? SM_EPI1 : SM_EPI0), ((c - 2) >> 1) & 1);
            const int eoff = s ? SM_E1 : SM_E0;
            const size_t gbase = (size_t)(c * BN) * D_DIM;
            #pragma unroll 4
            for (int i = lt; i < 4096; i += 96) {
                int row = i >> 5, c16 = i & 31;
                uint4 v = *reinterpret_cast<const uint4*>(g_Eb + gbase + (size_t)row * D_DIM + c16 * 8);
                *reinterpret_cast<uint4*>(smem + eoff + tile_off(row, c16 * 16)) = v;
            }
            if (lt < 32) {   // esq chunk: 128 floats
                float4 v = *reinterpret_cast<const float4*>(g_esq + c * BN + lt * 4);
                *reinterpret_cast<float4*>(smem + (s ? SM_ESQ1 : SM_ESQ0) + lt * 16) = v;
            }
            FENCE_ASYNC();
            MBAR_ARRIVE(sb + (s ? SM_FULL1 : SM_FULL0));
        }
    }

    __syncthreads();
    if (wid == 8) TC_DEALLOC(tmem, 256);
#else
    // Stub pass: force stage-2 exact full scan for correctness.
    if (tid < BM) {
        g_cand_cnt[(size_t)(rowBase + tid) * 2 + 0] = CAP_H + 1;
        g_cand_cnt[(size_t)(rowBase + tid) * 2 + 1] = CAP_H + 1;
    }
#endif
}

// ---------------- stage 2: exact fp32 rescore + gather ----------------
__global__ void vq_stage2(const float* __restrict__ X, const float* __restrict__ E,
                          float* __restrict__ out, int write_idx) {
    const int warp = (blockIdx.x * blockDim.x + threadIdx.x) >> 5;
    const int lane = threadIdx.x & 31;
    if (warp >= N_TOK) return;

    const float4* xr = reinterpret_cast<const float4*>(X + (size_t)warp * D_DIM) + lane * 2;
    const float4 x0 = xr[0], x1 = xr[1];

    float best = FLT_MAX;
    int bi = 0;

    auto score = [&](int k) -> float {
        const float4* er = reinterpret_cast<const float4*>(E + (size_t)k * D_DIM) + lane * 2;
        float4 e0 = er[0], e1 = er[1];
        float d = x0.x * e0.x;
        d = fmaf(x0.y, e0.y, d); d = fmaf(x0.z, e0.z, d); d = fmaf(x0.w, e0.w, d);
        d = fmaf(x1.x, e1.x, d); d = fmaf(x1.y, e1.y, d);
        d = fmaf(x1.z, e1.z, d); d = fmaf(x1.w, e1.w, d);
        #pragma unroll
        for (int o = 16; o > 0; o >>= 1) d += __shfl_xor_sync(0xFFFFFFFFu, d, o);
        return fmaf(-2.0f, d, __ldg(&g_esq[k]));
    };

    const int cnt0 = g_cand_cnt[(size_t)warp * 2 + 0];
    const int cnt1 = g_cand_cnt[(size_t)warp * 2 + 1];

    if (cnt0 <= CAP_H && cnt1 <= CAP_H) {
        const int* l0 = g_cand_idx + (size_t)warp * 2 * CAP_H;
        const int* l1 = l0 + CAP_H;
        for (int t = 0; t < cnt0; t++) {
            int k = l0[t];
            float scv = score(k);
            if (scv < best || (scv == best && k < bi)) { best = scv; bi = k; }
        }
        for (int t = 0; t < cnt1; t++) {
            int k = l1[t];
            float scv = score(k);
            if (scv < best || (scv == best && k < bi)) { best = scv; bi = k; }
        }
    } else {
        for (int k = 0; k < K_CB; k++) {
            float scv = score(k);
            if (scv < best) { best = scv; bi = k; }
        }
    }

    const float4* er = reinterpret_cast<const float4*>(E + (size_t)bi * D_DIM) + lane * 2;
    float4* outr = reinterpret_cast<float4*>(out + (size_t)warp * D_DIM) + lane * 2;
    outr[0] = er[0];
    outr[1] = er[1];
    if (write_idx && lane == 0)
        out[(size_t)N_TOK * D_DIM + warp] = (float)bi;
}

// ---------------- launcher ----------------
extern "C" void kernel_launch(void* const* d_in, const int* in_sizes, int n_in,
                              void* d_out, int out_size) {
    const float* X = (const float*)d_in[0];   // inputs_flatten [N, D]
    const float* E = (const float*)d_in[1];   // embed [K, D]
    float* out = (float*)d_out;

    cudaFuncSetAttribute(vq_stage1, cudaFuncAttributeMaxDynamicSharedMemorySize, SMEM_TOTAL);

    prep_x<<<(N_TOK * D_DIM / 8) / 256, 256>>>(X);
    prep_e<<<(K_CB * 32) / 256, 256>>>(E);
    vq_stage1<<<N_TOK / BM, NTHREADS, SMEM_TOTAL>>>();

    int write_idx = (out_size >= N_TOK * D_DIM + N_TOK) ? 1 : 0;
    vq_stage2<<<(N_TOK / 8), 256>>>(X, E, out, write_idx);
}